// round 5
// baseline (speedup 1.0000x reference)
#include <cuda_runtime.h>

#define KNB 16
typedef unsigned long long u64;

__device__ __align__(256) float g_fA[20096 * 128];
__device__ __align__(256) float g_fB[20096 * 128];

__device__ __forceinline__ float sigf(float x) {
    return __fdividef(1.0f, 1.0f + __expf(-x));
}
__device__ __forceinline__ float tanhfast(float x) {
    return __fdividef(2.0f, 1.0f + __expf(-2.0f * x)) - 1.0f;
}
// packed fp32x2 FMA: d.lo += a.lo*b.lo ; d.hi += a.hi*b.hi  (Blackwell FFMA2)
__device__ __forceinline__ void f2fma(u64& d, u64 a, u64 b) {
    asm("fma.rn.f32x2 %0, %1, %2, %0;" : "+l"(d) : "l"(a), "l"(b));
}
__device__ __forceinline__ u64 pack2(float lo, float hi) {
    u64 r; asm("mov.b64 %0, {%1, %2};" : "=l"(r) : "f"(lo), "f"(hi)); return r;
}
__device__ __forceinline__ float hadd2(u64 v) {
    float lo, hi; asm("mov.b64 {%0, %1}, %2;" : "=f"(lo), "=f"(hi) : "l"(v));
    return lo + hi;
}

__global__ void build_feat0(const float* __restrict__ p, float* __restrict__ f0, int nN) {
    int i = blockIdx.x * blockDim.x + threadIdx.x;
    if (i >= nN * 64) return;
    int node = i >> 6, k = i & 63;
    f0[i] = (k == 0) ? (16.0f / (float)nN) : p[node * 63 + (k - 1)];
}

// One GraphSAGE-LSTM layer. CTA: 144 nodes, 256 threads.
// thread (g=tid&15, ul=tid>>4) owns nodes g+16i (i<9), hidden unit ci*16+ul per chunk.
// Inner product done with packed fp32x2 FMAs (two k-lanes per instruction).
template <int DIN, int DOUT, bool RELU>
__global__ __launch_bounds__(256, 1)
void layer_k(const float* __restrict__ fin, const int* __restrict__ nidx,
             const float* __restrict__ Wih, const float* __restrict__ Whh,
             const float* __restrict__ bih, const float* __restrict__ bhh,
             const float* __restrict__ Wself, const float* __restrict__ Wneigh,
             const float* __restrict__ bo, float* __restrict__ fout, int nN)
{
    constexpr int TM = 144, NT = 256, NCH = DIN / 16, D4 = DIN / 4, P = 2 * D4 + 1;
    extern __shared__ float sm[];
    // XH: TM rows x P 16B-slots: [x(D4) | h(D4) | pad]; WC: 64 rows x P
    float4*     XH4 = (float4*)sm;
    ulonglong2* XHu = (ulonglong2*)sm;
    float4*     WC4 = XH4 + TM * P;
    ulonglong2* WCu = XHu + TM * P;
    float*      BS  = (float*)(WC4 + 64 * P);

    const int tid = threadIdx.x, g = tid & 15, ul = tid >> 4;
    const int node0 = blockIdx.x * TM;
    const float4* fin4 = (const float4*)fin;
    const float4* Wih4 = (const float4*)Wih;
    const float4* Whh4 = (const float4*)Whh;
    const float4* Wsf4 = (const float4*)Wself;
    const float4* Wng4 = (const float4*)Wneigh;

    const ulonglong2* xr[9];
#pragma unroll
    for (int i = 0; i < 9; i++) xr[i] = XHu + (g + 16 * i) * P;

    // init h = 0, combined LSTM bias
    for (int e = tid; e < TM * D4; e += NT)
        XH4[(e / D4) * P + D4 + (e % D4)] = make_float4(0.f, 0.f, 0.f, 0.f);
    for (int e = tid; e < 4 * DIN; e += NT) BS[e] = bih[e] + bhh[e];

    float c_[NCH][9], h_[NCH][9];
#pragma unroll 1
    for (int ci = 0; ci < NCH; ci++)
#pragma unroll
        for (int i = 0; i < 9; i++) { c_[ci][i] = 0.f; h_[ci][i] = 0.f; }

    for (int t = 0; t < KNB; t++) {
        __syncthreads();  // prior reads of XH done
        // gather step-t neighbor features into x-part
        for (int e = tid; e < TM * D4; e += NT) {
            int n = e / D4, k = e % D4;
            int nd = node0 + n; if (nd >= nN) nd = nN - 1;
            int src = nidx[nd * KNB + t];
            XH4[n * P + k] = fin4[src * D4 + k];
        }
#pragma unroll 1
        for (int ci = 0; ci < NCH; ci++) {
            __syncthreads();  // WC reads done (and gather visible at ci=0)
            for (int e = tid; e < 64 * 2 * D4; e += NT) {
                int r = e / (2 * D4), k = e % (2 * D4);
                int gr = (r >> 4) * DIN + ci * 16 + (r & 15);
                WC4[r * P + k] = (k < D4) ? Wih4[gr * D4 + k] : Whh4[gr * D4 + k - D4];
            }
            __syncthreads();
            const int u = ci * 16 + ul;
            u64 a0[9], a1[9], a2[9], a3[9];
            {
                u64 b0 = pack2(BS[u], 0.f),           b1 = pack2(BS[DIN + u], 0.f);
                u64 b2 = pack2(BS[2 * DIN + u], 0.f), b3 = pack2(BS[3 * DIN + u], 0.f);
#pragma unroll
                for (int i = 0; i < 9; i++) { a0[i] = b0; a1[i] = b1; a2[i] = b2; a3[i] = b3; }
            }
            const ulonglong2* w0 = WCu + (ul) * P;
            const ulonglong2* w1 = WCu + (16 + ul) * P;
            const ulonglong2* w2 = WCu + (32 + ul) * P;
            const ulonglong2* w3 = WCu + (48 + ul) * P;
#pragma unroll 2
            for (int k = 0; k < 2 * D4; k++) {
                ulonglong2 v0 = w0[k], v1 = w1[k], v2 = w2[k], v3 = w3[k];
#pragma unroll
                for (int i = 0; i < 9; i++) {
                    ulonglong2 x = xr[i][k];
                    f2fma(a0[i], x.x, v0.x); f2fma(a0[i], x.y, v0.y);
                    f2fma(a1[i], x.x, v1.x); f2fma(a1[i], x.y, v1.y);
                    f2fma(a2[i], x.x, v2.x); f2fma(a2[i], x.y, v2.y);
                    f2fma(a3[i], x.x, v3.x); f2fma(a3[i], x.y, v3.y);
                }
            }
#pragma unroll
            for (int i = 0; i < 9; i++) {
                float gi = hadd2(a0[i]), gf = hadd2(a1[i]);
                float gg = hadd2(a2[i]), go = hadd2(a3[i]);
                float cc = sigf(gf) * c_[ci][i] + sigf(gi) * tanhfast(gg);
                c_[ci][i] = cc;
                h_[ci][i] = sigf(go) * tanhfast(cc);
            }
        }
        __syncthreads();  // all XH reads done before h update
        float* XHs = (float*)XH4;
#pragma unroll 1
        for (int ci = 0; ci < NCH; ci++) {
            int u = ci * 16 + ul;
#pragma unroll
            for (int i = 0; i < 9; i++)
                XHs[(g + 16 * i) * (P * 4) + D4 * 4 + u] = h_[ci][i];
        }
    }

    // ---- FC epilogue: out = self_feat @ Wself^T + h @ Wneigh^T + b ----
    __syncthreads();
    for (int e = tid; e < TM * D4; e += NT) {  // overwrite x-part with self feature
        int n = e / D4, k = e % D4;
        int nd = node0 + n; if (nd >= nN) nd = nN - 1;
        XH4[n * P + k] = fin4[nd * D4 + k];
    }
    for (int ub = 0; ub < DOUT; ub += 64) {
        __syncthreads();
        for (int e = tid; e < 64 * 2 * D4; e += NT) {
            int r = e / (2 * D4), k = e % (2 * D4);
            int u = ub + r;
            if (u < DOUT)
                WC4[r * P + k] = (k < D4) ? Wsf4[u * D4 + k] : Wng4[u * D4 + k - D4];
        }
        __syncthreads();
#pragma unroll
        for (int q = 0; q < 4; q++) {
            int u = ub + q * 16 + ul;
            u64 acc[9];
            u64 bb = pack2((u < DOUT) ? bo[u] : 0.f, 0.f);
#pragma unroll
            for (int i = 0; i < 9; i++) acc[i] = bb;
            const ulonglong2* wr = WCu + (q * 16 + ul) * P;
#pragma unroll 2
            for (int k = 0; k < 2 * D4; k++) {
                ulonglong2 w = wr[k];
#pragma unroll
                for (int i = 0; i < 9; i++) {
                    ulonglong2 x = xr[i][k];
                    f2fma(acc[i], x.x, w.x);
                    f2fma(acc[i], x.y, w.y);
                }
            }
            if (u < DOUT) {
#pragma unroll
                for (int i = 0; i < 9; i++) {
                    int nd = node0 + g + 16 * i;
                    if (nd < nN) {
                        float v = hadd2(acc[i]);
                        if (RELU) v = fmaxf(v, 0.f);
                        fout[nd * DOUT + u] = v;
                    }
                }
            }
        }
    }
}

static int smem_bytes(int DIN) {
    int D4 = DIN / 4, P = 2 * D4 + 1;
    return (144 * P + 64 * P) * 16 + 4 * DIN * 4;
}

extern "C" void kernel_launch(void* const* d_in, const int* in_sizes, int n_in,
                              void* d_out, int out_size) {
    const float* p    = (const float*)d_in[0];
    const int*   nidx = (const int*)d_in[1];
    int nN = in_sizes[1] / KNB;

    float *fA, *fB;
    cudaGetSymbolAddress((void**)&fA, g_fA);
    cudaGetSymbolAddress((void**)&fB, g_fB);

    int sm64 = smem_bytes(64), sm128 = smem_bytes(128);
    cudaFuncSetAttribute(layer_k<64, 128, true>,  cudaFuncAttributeMaxDynamicSharedMemorySize, sm64);
    cudaFuncSetAttribute(layer_k<128, 128, true>, cudaFuncAttributeMaxDynamicSharedMemorySize, sm128);
    cudaFuncSetAttribute(layer_k<128, 32, false>, cudaFuncAttributeMaxDynamicSharedMemorySize, sm128);

    build_feat0<<<(nN * 64 + 255) / 256, 256>>>(p, fA, nN);

    int grid = (nN + 143) / 144;
    layer_k<64, 128, true><<<grid, 256, sm64>>>(
        fA, nidx,
        (const float*)d_in[2], (const float*)d_in[3], (const float*)d_in[4],
        (const float*)d_in[5], (const float*)d_in[6], (const float*)d_in[7],
        (const float*)d_in[8], fB, nN);
    layer_k<128, 128, true><<<grid, 256, sm128>>>(
        fB, nidx,
        (const float*)d_in[9], (const float*)d_in[10], (const float*)d_in[11],
        (const float*)d_in[12], (const float*)d_in[13], (const float*)d_in[14],
        (const float*)d_in[15], fA, nN);
    layer_k<128, 32, false><<<grid, 256, sm128>>>(
        fA, nidx,
        (const float*)d_in[16], (const float*)d_in[17], (const float*)d_in[18],
        (const float*)d_in[19], (const float*)d_in[20], (const float*)d_in[21],
        (const float*)d_in[22], (float*)d_out, nN);
}

// round 7
// speedup vs baseline: 2.7666x; 2.7666x over previous
#include <cuda_runtime.h>
#define KNB 16
typedef unsigned u32;

__device__ __align__(256) float g_fA[20096 * 128];
__device__ __align__(256) float g_fB[20096 * 128];

__device__ __forceinline__ float sigf(float x) { return __fdividef(1.f, 1.f + __expf(-x)); }
__device__ __forceinline__ float thf(float x)  { return __fdividef(2.f, 1.f + __expf(-2.f * x)) - 1.f; }
__device__ __forceinline__ u32 tf32r(float f) {
    u32 r; asm("cvt.rna.tf32.f32 %0, %1;" : "=r"(r) : "f"(f)); return r;
}
__device__ __forceinline__ uint4 tf32x4(float4 v) {
    return make_uint4(tf32r(v.x), tf32r(v.y), tf32r(v.z), tf32r(v.w));
}
// D(16x8) += A(16x8,row) * B(8x8,col) ; tf32 inputs, fp32 accum
__device__ __forceinline__ void mma8(float* d, const u32* a, const u32* b) {
    asm volatile("mma.sync.aligned.m16n8k8.row.col.f32.tf32.tf32.f32 "
        "{%0,%1,%2,%3},{%4,%5,%6,%7},{%8,%9},{%0,%1,%2,%3};"
        : "+f"(d[0]), "+f"(d[1]), "+f"(d[2]), "+f"(d[3])
        : "r"(a[0]), "r"(a[1]), "r"(a[2]), "r"(a[3]), "r"(b[0]), "r"(b[1]));
}

__global__ void build_feat0(const float* __restrict__ p, float* __restrict__ f0, int nN) {
    int i = blockIdx.x * blockDim.x + threadIdx.x;
    if (i >= nN * 64) return;
    int node = i >> 6, k = i & 63;
    f0[i] = (k == 0) ? (16.0f / (float)nN) : p[node * 63 + (k - 1)];
}

// One GraphSAGE-LSTM layer on the tensor pipe via mma.sync tf32.
// CTA: 144 nodes (9 m-tiles), 384 threads (12 warps). Warp w: mg=w%3 owns
// m-tiles 3mg..3mg+2 (rows 48mg..48mg+47), ng=w/3 owns n-tiles 2ng,2ng+1 of
// each 64-gate chunk. Gates interleaved per unit: col 4u+{i,f,g,o}.
template <int DIN, int DOUT, bool RELU>
__global__ __launch_bounds__(384, 1)
void layer_mma(const float* __restrict__ fin, const int* __restrict__ nidx,
               const float* __restrict__ Wih, const float* __restrict__ Whh,
               const float* __restrict__ bih, const float* __restrict__ bhh,
               const float* __restrict__ Wself, const float* __restrict__ Wneigh,
               const float* __restrict__ bo, float* __restrict__ fout, int nN)
{
    constexpr int TM = 144, NT = 384, KK = 2 * DIN, D4 = DIN / 4, K4 = KK / 4;
    constexpr int SX = KK + 4;                 // float stride; SX%32==4 -> conflict-free frags
    constexpr int NCH = DIN / 16;              // 64-gate chunks per step
    constexpr int NPRE = (16 * KK + NT - 1) / NT;  // float4 per thread per W chunk

    extern __shared__ float sm[];
    float* Xs = sm;            // TM x SX : [x(DIN) | h(DIN) | pad]
    float* Ws = sm + TM * SX;  // 64 x SX : W chunk (tf32)
    __shared__ float BSI[512];
    __shared__ float BOs[128];

    const int tid = threadIdx.x, lane = tid & 31, w = tid >> 5;
    const int gq = lane >> 2, tq = lane & 3;
    const int mg = w % 3, ng = w / 3;
    const int MB = 48 * mg;
    const int node0 = blockIdx.x * TM;
    const float4* fin4 = (const float4*)fin;
    const float4* Wi4 = (const float4*)Wih;
    const float4* Wh4 = (const float4*)Whh;
    const float4* Wsf4 = (const float4*)Wself;
    const float4* Wng4 = (const float4*)Wneigh;

    // bias (interleaved: BSI[4u+q]), zero h, gather x(0)
    for (int e = tid; e < 4 * DIN; e += NT)
        BSI[e] = bih[(e & 3) * DIN + (e >> 2)] + bhh[(e & 3) * DIN + (e >> 2)];
    if (tid < DOUT) BOs[tid] = bo[tid];
    for (int e = tid; e < TM * D4; e += NT)
        ((uint4*)(Xs + (e / D4) * SX + DIN))[e % D4] = make_uint4(0, 0, 0, 0);
    for (int e = tid; e < TM * D4; e += NT) {
        int row = e / D4, k4 = e % D4;
        int nd = node0 + row; if (nd >= nN) nd = nN - 1;
        ((uint4*)(Xs + row * SX))[k4] = tf32x4(fin4[nidx[nd * KNB + 0] * D4 + k4]);
    }

    float c_loc[NCH][6], h_loc[NCH][6];
#pragma unroll 1
    for (int ci = 0; ci < NCH; ci++)
#pragma unroll
        for (int i = 0; i < 6; i++) c_loc[ci][i] = 0.f;

    // prefetch W chunk 0
    float4 pre[NPRE];
#pragma unroll
    for (int i = 0; i < NPRE; i++) {
        int idx = tid + i * NT;
        if (idx < 16 * KK) {
            int r = idx / K4, c4 = idx % K4;
            int wr = (r & 3) * DIN + (r >> 2);   // chunk 0
            pre[i] = (c4 < D4) ? Wi4[wr * D4 + c4] : Wh4[wr * D4 + c4 - D4];
        }
    }

    const float* pA0 = Xs + (MB + gq) * SX + tq;
    const float* pB0 = Ws + (16 * ng + gq) * SX + tq;

    for (int t = 0; t < KNB; t++) {
#pragma unroll 1
        for (int ci = 0; ci < NCH; ci++) {
            __syncthreads();   // Ws free / Xs writes visible
#pragma unroll
            for (int i = 0; i < NPRE; i++) {
                int idx = tid + i * NT;
                if (idx < 16 * KK)
                    ((uint4*)(Ws + (idx / K4) * SX))[idx % K4] = tf32x4(pre[i]);
            }
            __syncthreads();
            // prefetch next chunk (wraps to 0 for next step)
            int cn = (ci + 1 < NCH) ? ci + 1 : 0;
#pragma unroll
            for (int i = 0; i < NPRE; i++) {
                int idx = tid + i * NT;
                if (idx < 16 * KK) {
                    int r = idx / K4, c4 = idx % K4;
                    int wr = (r & 3) * DIN + cn * 16 + (r >> 2);
                    pre[i] = (c4 < D4) ? Wi4[wr * D4 + c4] : Wh4[wr * D4 + c4 - D4];
                }
            }
            // D init with bias
            float D[3][2][4];
#pragma unroll
            for (int nt = 0; nt < 2; nt++) {
                float b0 = BSI[ci * 64 + 16 * ng + 8 * nt + 2 * tq];
                float b1 = BSI[ci * 64 + 16 * ng + 8 * nt + 2 * tq + 1];
#pragma unroll
                for (int mi = 0; mi < 3; mi++) {
                    D[mi][nt][0] = b0; D[mi][nt][1] = b1;
                    D[mi][nt][2] = b0; D[mi][nt][3] = b1;
                }
            }
            // k loop
#pragma unroll 4
            for (int k0 = 0; k0 < KK; k0 += 8) {
                u32 a[3][4], b[2][2];
#pragma unroll
                for (int mi = 0; mi < 3; mi++) {
                    const float* pa = pA0 + 16 * mi * SX + k0;
                    a[mi][0] = __float_as_uint(pa[0]);
                    a[mi][1] = __float_as_uint(pa[8 * SX]);
                    a[mi][2] = __float_as_uint(pa[4]);
                    a[mi][3] = __float_as_uint(pa[8 * SX + 4]);
                }
#pragma unroll
                for (int nt = 0; nt < 2; nt++) {
                    const float* pb = pB0 + 8 * nt * SX + k0;
                    b[nt][0] = __float_as_uint(pb[0]);
                    b[nt][1] = __float_as_uint(pb[4]);
                }
#pragma unroll
                for (int mi = 0; mi < 3; mi++)
#pragma unroll
                    for (int nt = 0; nt < 2; nt++) mma8(D[mi][nt], a[mi], b[nt]);
            }
            // epilogue: reassemble gates via shfl, update c/h
#pragma unroll
            for (int mi = 0; mi < 3; mi++)
#pragma unroll
                for (int nt = 0; nt < 2; nt++) {
                    float d0 = D[mi][nt][0], d1 = D[mi][nt][1];
                    float d2 = D[mi][nt][2], d3 = D[mi][nt][3];
                    float x0 = __shfl_xor_sync(0xffffffffu, d0, 1);
                    float x1 = __shfl_xor_sync(0xffffffffu, d1, 1);
                    float x2 = __shfl_xor_sync(0xffffffffu, d2, 1);
                    float x3 = __shfl_xor_sync(0xffffffffu, d3, 1);
                    float gi, gf, gg, go;
                    if (!(tq & 1)) { gi = d0; gf = d1; gg = x0; go = x1; }  // row MB+16mi+gq
                    else           { gi = x2; gf = x3; gg = d2; go = d3; }  // row +8
                    float cc = sigf(gf) * c_loc[ci][mi * 2 + nt] + sigf(gi) * thf(gg);
                    c_loc[ci][mi * 2 + nt] = cc;
                    h_loc[ci][mi * 2 + nt] = __uint_as_float(tf32r(sigf(go) * thf(cc)));
                }
        }
        __syncthreads();  // all k-loop reads of h(t-1)/x(t) done
        // write back h(t)
#pragma unroll 1
        for (int ci = 0; ci < NCH; ci++)
#pragma unroll
            for (int mi = 0; mi < 3; mi++)
#pragma unroll
                for (int nt = 0; nt < 2; nt++) {
                    int row = MB + 16 * mi + gq + ((tq & 1) ? 8 : 0);
                    int u = ci * 16 + 4 * ng + 2 * nt + (tq >> 1);
                    Xs[row * SX + DIN + u] = h_loc[ci][mi * 2 + nt];
                }
        if (t + 1 < KNB) {  // gather x(t+1)
            for (int e = tid; e < TM * D4; e += NT) {
                int row = e / D4, k4 = e % D4;
                int nd = node0 + row; if (nd >= nN) nd = nN - 1;
                ((uint4*)(Xs + row * SX))[k4] = tf32x4(fin4[nidx[nd * KNB + t + 1] * D4 + k4]);
            }
        }
    }

    // ---- FC: out = [self_feat | h_final] @ [Wself|Wneigh]^T + b ----
    __syncthreads();
    for (int e = tid; e < TM * D4; e += NT) {
        int row = e / D4, k4 = e % D4;
        int nd = node0 + row; if (nd >= nN) nd = nN - 1;
        ((uint4*)(Xs + row * SX))[k4] = tf32x4(fin4[nd * D4 + k4]);
    }
    for (int ub = 0; ub < DOUT; ub += 64) {
        const int CR = (DOUT - ub < 64) ? (DOUT - ub) : 64;
        const int NTW = CR / 32;   // 2 (CR=64) or 1 (CR=32)
        __syncthreads();
        for (int e = tid; e < CR * K4; e += NT) {
            int r = e / K4, c4 = e % K4;
            int wr = ub + r;
            float4 v = (c4 < D4) ? Wsf4[wr * D4 + c4] : Wng4[wr * D4 + c4 - D4];
            ((uint4*)(Ws + r * SX))[c4] = tf32x4(v);
        }
        __syncthreads();
        float D[3][2][4];
        for (int nt = 0; nt < NTW; nt++) {
            int cb = 8 * (NTW * ng + nt);
            float b0 = BOs[ub + cb + 2 * tq], b1 = BOs[ub + cb + 2 * tq + 1];
#pragma unroll
            for (int mi = 0; mi < 3; mi++) {
                D[mi][nt][0] = b0; D[mi][nt][1] = b1;
                D[mi][nt][2] = b0; D[mi][nt][3] = b1;
            }
        }
#pragma unroll 4
        for (int k0 = 0; k0 < KK; k0 += 8) {
            u32 a[3][4], b[2][2];
#pragma unroll
            for (int mi = 0; mi < 3; mi++) {
                const float* pa = pA0 + 16 * mi * SX + k0;
                a[mi][0] = __float_as_uint(pa[0]);
                a[mi][1] = __float_as_uint(pa[8 * SX]);
                a[mi][2] = __float_as_uint(pa[4]);
                a[mi][3] = __float_as_uint(pa[8 * SX + 4]);
            }
            for (int nt = 0; nt < NTW; nt++) {
                const float* pb = Ws + (8 * (NTW * ng + nt) + gq) * SX + tq + k0;
                b[nt][0] = __float_as_uint(pb[0]);
                b[nt][1] = __float_as_uint(pb[4]);
            }
#pragma unroll
            for (int mi = 0; mi < 3; mi++)
                for (int nt = 0; nt < NTW; nt++) mma8(D[mi][nt], a[mi], b[nt]);
        }
#pragma unroll
        for (int mi = 0; mi < 3; mi++)
            for (int nt = 0; nt < NTW; nt++) {
                int col = ub + 8 * (NTW * ng + nt) + 2 * tq;
                int r0 = node0 + MB + 16 * mi + gq;
#pragma unroll
                for (int jj = 0; jj < 4; jj++) {
                    int nd = r0 + ((jj >> 1) ? 8 : 0);
                    if (nd < nN) {
                        float v = D[mi][nt][jj];
                        if (RELU) v = fmaxf(v, 0.f);
                        fout[nd * DOUT + col + (jj & 1)] = v;
                    }
                }
            }
    }
}

extern "C" void kernel_launch(void* const* d_in, const int* in_sizes, int n_in,
                              void* d_out, int out_size) {
    const float* p  = (const float*)d_in[0];
    const int* nidx = (const int*)d_in[1];
    int nN = in_sizes[1] / KNB;

    float *fA, *fB;
    cudaGetSymbolAddress((void**)&fA, g_fA);
    cudaGetSymbolAddress((void**)&fB, g_fB);

    int smA = (144 + 64) * (2 * 64 + 4) * 4;    // DIN=64  -> 109,824
    int smB = (144 + 64) * (2 * 128 + 4) * 4;   // DIN=128 -> 216,320
    cudaFuncSetAttribute(layer_mma<64, 128, true>,  cudaFuncAttributeMaxDynamicSharedMemorySize, smA);
    cudaFuncSetAttribute(layer_mma<128, 128, true>, cudaFuncAttributeMaxDynamicSharedMemorySize, smB);
    cudaFuncSetAttribute(layer_mma<128, 32, false>, cudaFuncAttributeMaxDynamicSharedMemorySize, smB);

    build_feat0<<<(nN * 64 + 255) / 256, 256>>>(p, fA, nN);

    int grid = (nN + 143) / 144;
    layer_mma<64, 128, true><<<grid, 384, smA>>>(
        fA, nidx, (const float*)d_in[2], (const float*)d_in[3], (const float*)d_in[4],
        (const float*)d_in[5], (const float*)d_in[6], (const float*)d_in[7],
        (const float*)d_in[8], fB, nN);
    layer_mma<128, 128, true><<<grid, 384, smB>>>(
        fB, nidx, (const float*)d_in[9], (const float*)d_in[10], (const float*)d_in[11],
        (const float*)d_in[12], (const float*)d_in[13], (const float*)d_in[14],
        (const float*)d_in[15], fA, nN);
    layer_mma<128, 32, false><<<grid, 384, smB>>>(
        fA, nidx, (const float*)d_in[16], (const float*)d_in[17], (const float*)d_in[18],
        (const float*)d_in[19], (const float*)d_in[20], (const float*)d_in[21],
        (const float*)d_in[22], (float*)d_out, nN);
}